// round 8
// baseline (speedup 1.0000x reference)
#include <cuda_runtime.h>

#define FULL 0xffffffffu

// Softmax over 16-lane groups for two values at once (x, y one per lane).
// Max phase packed as truncated-bf16 halves (max only controls exp range;
// softmax is shift-invariant, so result is exact).
__device__ __forceinline__ void softmax16_pair(float x, float y, float &px, float &py) {
    unsigned m = (__float_as_uint(x) & 0xFFFF0000u) | (__float_as_uint(y) >> 16);
    m = __vmaxu2(m, __shfl_xor_sync(FULL, m, 1));
    m = __vmaxu2(m, __shfl_xor_sync(FULL, m, 2));
    m = __vmaxu2(m, __shfl_xor_sync(FULL, m, 4));
    m = __vmaxu2(m, __shfl_xor_sync(FULL, m, 8));
    float mx = __uint_as_float(m & 0xFFFF0000u);
    float my = __uint_as_float(m << 16);
    float ex = __expf(100.f * (x - mx));
    float ey = __expf(100.f * (y - my));
    float sx = ex, sy = ey;
    sx += __shfl_xor_sync(FULL, sx, 1);  sy += __shfl_xor_sync(FULL, sy, 1);
    sx += __shfl_xor_sync(FULL, sx, 2);  sy += __shfl_xor_sync(FULL, sy, 2);
    sx += __shfl_xor_sync(FULL, sx, 4);  sy += __shfl_xor_sync(FULL, sy, 4);
    sx += __shfl_xor_sync(FULL, sx, 8);  sy += __shfl_xor_sync(FULL, sy, 8);
    px = __fdividef(ex, sx);
    py = __fdividef(ey, sy);
}

// Single-stream softmax over each 16-lane group (one value per lane).
__device__ __forceinline__ float softmax16(float x) {
    float m = x;
    m = fmaxf(m, __shfl_xor_sync(FULL, m, 1));
    m = fmaxf(m, __shfl_xor_sync(FULL, m, 2));
    m = fmaxf(m, __shfl_xor_sync(FULL, m, 4));
    m = fmaxf(m, __shfl_xor_sync(FULL, m, 8));
    float e = __expf(100.f * (x - m));
    float s = e;
    s += __shfl_xor_sync(FULL, s, 1);
    s += __shfl_xor_sync(FULL, s, 2);
    s += __shfl_xor_sync(FULL, s, 4);
    s += __shfl_xor_sync(FULL, s, 8);
    return __fdividef(e, s);
}

// One warp per batch element, 8 warps/block, zero barriers (warp-sync only).
// Per-warp smem layout (floats):
//   [ 0..15]  paL   (banks  0-15)     [16..31] paH (banks 16-31)
//   [48..63]  pbL   (banks 16-31)     [64..79] pbH (banks  0-15)
//   [96..111] psl                     [112..127] psh
__global__ void __launch_bounds__(256, 7) nalu_kernel(
        const float* __restrict__ A, const float* __restrict__ Bq,
        float* __restrict__ O, int B) {
    __shared__ float smem[8][128];
    const int lane = threadIdx.x & 31;
    const int n = blockIdx.x * 8 + (threadIdx.x >> 5);
    if (n >= B) return;
    float* ws = smem[threadIdx.x >> 5];

    const bool lo   = lane < 16;
    const int  l15  = lane & 15;
    const int  hi16 = lane & 16;
    const bool b0 = lane & 1, b1 = lane & 2, b2 = lane & 4, b3 = lane & 8;
    // low-sum inverse permutation: lane s holds col c(s)=4(s&3)+2*bit2(s)+bit3(s)
    const int srcL   = ((l15 >> 2) | ((l15 & 2) << 1) | ((l15 & 1) << 3)) | hi16;
    // high-sum distribute: lane 4r+{0,1,2,3} = {ha[r], hb[r], ha[8+r], hb[8+r]}
    const int srcH   = 4 * (l15 & 7) + 2 * ((l15 >> 3) & 1) + (lo ? 0 : 1);
    const int srcV   = ((l15 + 15) & 15) | hi16;            // v[s] = u[(s-1)&15], per half

    // smem address constants
    float* stPL = ws + (lo ? l15 : 48 + l15);      // pl staging slot
    float* stPH = ws + (lo ? 16 + l15 : 64 + l15); // ph staging slot
    const float*  paT = ws + (lo ? 0 : 16);        // pa table base for this half
    const float4* pbT = (const float4*)(ws + (lo ? 48 : 64));  // pb table (uniform per half)
    const int lb = (lane & 1) * 8;
    const float4* po4 = (const float4*)(ws + 96 + lb);
    const float*  pshp = ws + 112 + (lane >> 1);

    const float4* a4 = (const float4*)(A  + (size_t)n * 1024);
    const float4* b4 = (const float4*)(Bq + (size_t)n * 1024);
    float* orow = O + (size_t)n * 1024 + lane * 8;

    float c1 = 0.f;  // P(carry=1); carry starts one-hot [1,0]

#pragma unroll 1
    for (int i = 0; i < 4; i++) {
        float4 av0 = a4[i * 64 + lane];
        float4 av1 = a4[i * 64 + 32 + lane];
        float4 bv0 = b4[i * 64 + lane];
        float4 bv1 = b4[i * 64 + 32 + lane];

        // ---- low-nibble sums via reduce-scatter ----
        float la0 = av0.x + av1.x, la1 = av0.y + av1.y;
        float la2 = av0.z + av1.z, la3 = av0.w + av1.w;
        float lb0 = bv0.x + bv1.x, lb1 = bv0.y + bv1.y;
        float lb2 = bv0.z + bv1.z, lb3 = bv0.w + bv1.w;
        float t0 = (lo ? la0 : lb0) + __shfl_xor_sync(FULL, lo ? lb0 : la0, 16);
        float t1 = (lo ? la1 : lb1) + __shfl_xor_sync(FULL, lo ? lb1 : la1, 16);
        float t2 = (lo ? la2 : lb2) + __shfl_xor_sync(FULL, lo ? lb2 : la2, 16);
        float t3 = (lo ? la3 : lb3) + __shfl_xor_sync(FULL, lo ? lb3 : la3, 16);
        float ra = __shfl_xor_sync(FULL, b2 ? t0 : t2, 4);
        float rb = __shfl_xor_sync(FULL, b2 ? t1 : t3, 4);
        float pp = (b2 ? t2 : t0) + ra;
        float qq = (b2 ? t3 : t1) + rb;
        float rc = __shfl_xor_sync(FULL, b3 ? pp : qq, 8);
        float lres = (b3 ? qq : pp) + rc;
        float lv = __shfl_sync(FULL, lres, srcL);

        // ---- high-nibble sums via reduce-scatter ----
        float hp0a = (av0.x + av0.y) + (av0.z + av0.w);
        float hp1a = (av1.x + av1.y) + (av1.z + av1.w);
        float hp0b = (bv0.x + bv0.y) + (bv0.z + bv0.w);
        float hp1b = (bv1.x + bv1.y) + (bv1.z + bv1.w);
        float ga = __shfl_xor_sync(FULL, b0 ? hp0a : hp0b, 1);
        float gb = __shfl_xor_sync(FULL, b0 ? hp1a : hp1b, 1);
        float hpA = (b0 ? hp0b : hp0a) + ga;
        float hpB = (b0 ? hp1b : hp1a) + gb;
        float gc = __shfl_xor_sync(FULL, b1 ? hpA : hpB, 2);
        float hres = (b1 ? hpB : hpA) + gc;
        float hv = __shfl_sync(FULL, hres, srcH);

        // ---- input softmaxes: pl/ph hold pa (lanes 0-15) | pb (16-31) ----
        float ph, pl;
        softmax16_pair(hv, lv, ph, pl);

        // ---- stage tables: paL|pbL from pl, paH|pbH from ph ----
        *stPL = pl;
        *stPH = ph;
        __syncwarp();

        // ---- merged cyclic convs via smem (L on lower half, H on upper) ----
        // u1: j<=s taps, u2: j>s (wrap) taps; pa[(s-j)&15] scalar LDS (conflict-free),
        // pb[j] uniform LDS.128 -> static register index.
        float u1, u2 = 0.f;
        {
            float4 pbA = pbT[0], pbB = pbT[1];
            u1 = paT[l15] * pbA.x;                                   // j=0
#define TAP(j, bj) { float pav = paT[(l15 - (j)) & 15]; \
                     if ((j) <= l15) u1 = fmaf(pav, (bj), u1); \
                     else            u2 = fmaf(pav, (bj), u2); }
            TAP(1, pbA.y)  TAP(2, pbA.z)  TAP(3, pbA.w)
            TAP(4, pbB.x)  TAP(5, pbB.y)  TAP(6, pbB.z)  TAP(7, pbB.w)
        }
        {
            float4 pbC = pbT[2], pbD = pbT[3];
            TAP(8,  pbC.x) TAP(9,  pbC.y) TAP(10, pbC.z) TAP(11, pbC.w)
            TAP(12, pbD.x) TAP(13, pbD.y) TAP(14, pbD.z) TAP(15, pbD.w)
#undef TAP
        }
        float u = u1 + u2;
        // u: uL[s] on lane s, uH[s] on lane 16+s; R0 = sum_s u2[s] per half
        u2 += __shfl_xor_sync(FULL, u2, 1);
        u2 += __shfl_xor_sync(FULL, u2, 2);
        u2 += __shfl_xor_sync(FULL, u2, 4);
        u2 += __shfl_xor_sync(FULL, u2, 8);
        float wx = __shfl_xor_sync(FULL, u2, 16);
        float r0L = lo ? u2 : wx;
        float r0H = lo ? wx : u2;

        float v    = __shfl_sync(FULL, u, srcV);   // vl lower | vh upper
        float u15L = __shfl_sync(FULL, u, 15);
        float u15H = __shfl_sync(FULL, u, 31);

        // ---- serial carry chain (lane-uniform scalars) ----
        float pc1L = __fdividef(1.f, 1.f + __expf(100.f * (1.f - 2.f * c1)));
        float pc0L = 1.f - pc1L;
        c1 = fmaf(pc0L, r0L, pc1L * (r0L + u15L));
        float pc1H = __fdividef(1.f, 1.f + __expf(100.f * (1.f - 2.f * c1)));
        float pc0H = 1.f - pc1H;
        c1 = fmaf(pc0H, r0H, pc1H * (r0H + u15H));

        // per-half blended sums: sl on lower half, sh on upper half
        float x = lo ? fmaf(pc0L, u, pc1L * v)
                     : fmaf(pc0H, u, pc1H * v);

        // ---- output softmax: psl on lower half, psh on upper half ----
        float p_out = softmax16(x);

        // ---- outer product via smem: out[h*16+l] = psh[h]*psl[l] ----
        // lane covers h = lane>>1, l in [lb, lb+8)
        ws[96 + lane] = p_out;
        __syncwarp();
        float4 o0 = po4[0];
        float4 o1 = po4[1];
        float hvv = *pshp;
        o0.x *= hvv;  o0.y *= hvv;  o0.z *= hvv;  o0.w *= hvv;
        o1.x *= hvv;  o1.y *= hvv;  o1.z *= hvv;  o1.w *= hvv;
        ((float4*)(orow + i * 256))[0] = o0;
        ((float4*)(orow + i * 256))[1] = o1;
        __syncwarp();   // protect tables from next iteration's overwrite
    }
}

extern "C" void kernel_launch(void* const* d_in, const int* in_sizes, int n_in,
                              void* d_out, int out_size) {
    const float* A  = (const float*)d_in[0];
    const float* Bq = (const float*)d_in[1];
    float* O = (float*)d_out;
    int B = in_sizes[0] / 1024;          // [B, 4, 256]
    dim3 grid((B + 7) / 8);
    nalu_kernel<<<grid, 256>>>(A, Bq, O, B);
}

// round 9
// speedup vs baseline: 1.0936x; 1.0936x over previous
#include <cuda_runtime.h>

#define FULL 0xffffffffu

// Softmax over 16-lane groups for two values at once (x, y one per lane).
// Max phase packed as truncated-bf16 halves (max only controls exp range;
// softmax is shift-invariant, so result is exact).
__device__ __forceinline__ void softmax16_pair(float x, float y, float &px, float &py) {
    unsigned m = (__float_as_uint(x) & 0xFFFF0000u) | (__float_as_uint(y) >> 16);
    m = __vmaxu2(m, __shfl_xor_sync(FULL, m, 1));
    m = __vmaxu2(m, __shfl_xor_sync(FULL, m, 2));
    m = __vmaxu2(m, __shfl_xor_sync(FULL, m, 4));
    m = __vmaxu2(m, __shfl_xor_sync(FULL, m, 8));
    float mx = __uint_as_float(m & 0xFFFF0000u);
    float my = __uint_as_float(m << 16);
    float ex = __expf(100.f * (x - mx));
    float ey = __expf(100.f * (y - my));
    float sx = ex, sy = ey;
    sx += __shfl_xor_sync(FULL, sx, 1);  sy += __shfl_xor_sync(FULL, sy, 1);
    sx += __shfl_xor_sync(FULL, sx, 2);  sy += __shfl_xor_sync(FULL, sy, 2);
    sx += __shfl_xor_sync(FULL, sx, 4);  sy += __shfl_xor_sync(FULL, sy, 4);
    sx += __shfl_xor_sync(FULL, sx, 8);  sy += __shfl_xor_sync(FULL, sy, 8);
    px = __fdividef(ex, sx);
    py = __fdividef(ey, sy);
}

// Single-stream softmax over each 16-lane group (one value per lane).
__device__ __forceinline__ float softmax16(float x) {
    float m = x;
    m = fmaxf(m, __shfl_xor_sync(FULL, m, 1));
    m = fmaxf(m, __shfl_xor_sync(FULL, m, 2));
    m = fmaxf(m, __shfl_xor_sync(FULL, m, 4));
    m = fmaxf(m, __shfl_xor_sync(FULL, m, 8));
    float e = __expf(100.f * (x - m));
    float s = e;
    s += __shfl_xor_sync(FULL, s, 1);
    s += __shfl_xor_sync(FULL, s, 2);
    s += __shfl_xor_sync(FULL, s, 4);
    s += __shfl_xor_sync(FULL, s, 8);
    return __fdividef(e, s);
}

// One warp per batch element, 8 warps/block.
// Lanes 0-15 own the A row, lanes 16-31 the B row (column-strided float4s).
// Per-warp smem (192 floats): pb tables 2x64 (double-buffered: [pbL0..15 | pbH0..15]
// padded to 64), out staging 2x32.
__global__ void __launch_bounds__(256, 7) nalu_kernel(
        const float* __restrict__ A, const float* __restrict__ Bq,
        float* __restrict__ O, int B) {
    __shared__ float smem[8][192];
    const int lane = threadIdx.x & 31;
    const int n = blockIdx.x * 8 + (threadIdx.x >> 5);
    if (n >= B) return;
    float* ws = smem[threadIdx.x >> 5];

    const bool lo   = lane < 16;
    const int  l15  = lane & 15;
    const int  hi16 = lane & 16;
    const bool b0 = lane & 1, b1 = lane & 2, b2 = lane & 4, b3 = lane & 8;
    const int srcRot = ((l15 - 1) & 15) | hi16;             // pa rotate-down per half
    // low-sum gather: lane owning la[l15]
    const int srcL   = ((l15 >> 2) | ((l15 & 2) << 1) | ((l15 & 1) << 3)) | hi16;
    // high-sum gather: lane owning ha[l15]
    const int srcH   = (4 * (l15 & 3) + ((l15 >> 3) & 1) + 2 * ((l15 >> 2) & 1)) | hi16;
    const int srcV   = ((l15 + 15) & 15) | hi16;            // v[s] = u[(s-1)&15]

    // loads: lower half reads A, upper half reads B, column-strided float4s
    const float4* rowbase = (const float4*)((lo ? A : Bq) + (size_t)n * 1024);
    float* orow = O + (size_t)n * 1024 + lane * 8;

    // smem pointer pieces (buffer offset added per iteration)
    float* stPB   = ws + l15;                 // upper half stores pbL here, pbH at +16
    const int pbRd = lo ? 0 : 16;             // conv tap table base per half
    const int lb   = (lane & 1) * 8;
    const int hvOff = 16 + (lane >> 1);

    float c1 = 0.f;  // P(carry=1); carry starts one-hot [1,0]

#pragma unroll 1
    for (int i = 0; i < 4; i++) {
        const float4* r4 = rowbase + i * 64;
        float4 av0 = r4[l15];
        float4 av1 = r4[16 + l15];
        float4 av2 = r4[32 + l15];
        float4 av3 = r4[48 + l15];
        const int ib  = (i & 1) << 6;          // pb buffer offset (0/64)
        const int ob  = 128 + ((i & 1) << 5);  // out buffer offset (128/160)

        // ---- low-nibble sums: la_k covers l = 4*(l15&3)+k ----
        float la0 = (av0.x + av1.x) + (av2.x + av3.x);
        float la1 = (av0.y + av1.y) + (av2.y + av3.y);
        float la2 = (av0.z + av1.z) + (av2.z + av3.z);
        float la3 = (av0.w + av1.w) + (av2.w + av3.w);
        // reduce over lanes {s, s^4, s^8}: keep k-pair by b2, then k by b3
        float w0 = (b2 ? la2 : la0) + __shfl_xor_sync(FULL, b2 ? la0 : la2, 4);
        float w1 = (b2 ? la3 : la1) + __shfl_xor_sync(FULL, b2 ? la1 : la3, 4);
        float lres = (b3 ? w1 : w0) + __shfl_xor_sync(FULL, b3 ? w0 : w1, 8);
        float lv = __shfl_sync(FULL, lres, srcL);          // la[l15] (a|b by half)

        // ---- high-nibble sums: hp_r covers h = 4r + (l15>>2) ----
        float hp0 = (av0.x + av0.y) + (av0.z + av0.w);
        float hp1 = (av1.x + av1.y) + (av1.z + av1.w);
        float hp2 = (av2.x + av2.y) + (av2.z + av2.w);
        float hp3 = (av3.x + av3.y) + (av3.z + av3.w);
        // reduce over quad {s, s^1, s^2}: keep r-pair by b0, then r by b1
        float z0 = (b0 ? hp2 : hp0) + __shfl_xor_sync(FULL, b0 ? hp0 : hp2, 1);
        float z1 = (b0 ? hp3 : hp1) + __shfl_xor_sync(FULL, b0 ? hp1 : hp3, 1);
        float hres = (b1 ? z1 : z0) + __shfl_xor_sync(FULL, b1 ? z0 : z1, 2);
        float hv = __shfl_sync(FULL, hres, srcH);          // ha[l15] (a|b by half)

        // ---- input softmaxes: pl/ph hold pa (lanes 0-15) | pb (16-31) ----
        float ph, pl;
        softmax16_pair(hv, lv, ph, pl);

        // ---- stage pb tables (upper half holds pbL in pl, pbH in ph) ----
        if (!lo) {
            stPB[ib]      = pl;    // pbL[l15]
            stPB[ib + 16] = ph;    // pbH[l15]
        }
        // q: lane s -> paL[s], lane 16+s -> paH[s]
        float qshf = __shfl_sync(FULL, ph, l15);
        float q    = lo ? pl : qshf;
        __syncwarp();

        // ---- merged cyclic convs: L on lower half, H on upper ----
        // pa rotates in registers; pb taps via uniform LDS.128 (4 per half)
        const float4* pbT = (const float4*)(ws + ib + pbRd);
        float u1, u2 = 0.f;   // u1: j<=s taps, u2: j>s (wrap) taps
        {
            float4 pbA = pbT[0], pbB = pbT[1];
            u1 = q * pbA.x;                                      // j=0
            q = __shfl_sync(FULL, q, srcRot);
#define TAP(j, bj) { if ((j) <= l15) u1 = fmaf(q, (bj), u1); \
                     else            u2 = fmaf(q, (bj), u2); \
                     if ((j) < 15) q = __shfl_sync(FULL, q, srcRot); }
            TAP(1, pbA.y)  TAP(2, pbA.z)  TAP(3, pbA.w)
            TAP(4, pbB.x)  TAP(5, pbB.y)  TAP(6, pbB.z)  TAP(7, pbB.w)
        }
        {
            float4 pbC = pbT[2], pbD = pbT[3];
            TAP(8,  pbC.x) TAP(9,  pbC.y) TAP(10, pbC.z) TAP(11, pbC.w)
            TAP(12, pbD.x) TAP(13, pbD.y) TAP(14, pbD.z) TAP(15, pbD.w)
#undef TAP
        }
        float u = u1 + u2;
        // u: uL[s] on lane s, uH[s] on lane 16+s; R0 = sum_s u2[s] per half
        u2 += __shfl_xor_sync(FULL, u2, 1);
        u2 += __shfl_xor_sync(FULL, u2, 2);
        u2 += __shfl_xor_sync(FULL, u2, 4);
        u2 += __shfl_xor_sync(FULL, u2, 8);
        float wx = __shfl_xor_sync(FULL, u2, 16);
        float r0L = lo ? u2 : wx;
        float r0H = lo ? wx : u2;

        float v    = __shfl_sync(FULL, u, srcV);   // vl lower | vh upper
        float u15L = __shfl_sync(FULL, u, 15);
        float u15H = __shfl_sync(FULL, u, 31);

        // ---- serial carry chain (lane-uniform scalars) ----
        float pc1L = __fdividef(1.f, 1.f + __expf(100.f * (1.f - 2.f * c1)));
        float pc0L = 1.f - pc1L;
        c1 = fmaf(pc0L, r0L, pc1L * (r0L + u15L));
        float pc1H = __fdividef(1.f, 1.f + __expf(100.f * (1.f - 2.f * c1)));
        float pc0H = 1.f - pc1H;
        c1 = fmaf(pc0H, r0H, pc1H * (r0H + u15H));

        // per-half blended sums: sl on lower half, sh on upper half
        float x = lo ? fmaf(pc0L, u, pc1L * v)
                     : fmaf(pc0H, u, pc1H * v);

        // ---- output softmax: psl on lower half, psh on upper half ----
        float p_out = softmax16(x);

        // ---- outer product via smem: out[h*16+l] = psh[h]*psl[l] ----
        ws[ob + lane] = p_out;       // [0..15]=psl, [16..31]=psh
        __syncwarp();
        const float4* po4 = (const float4*)(ws + ob + lb);
        float4 o0 = po4[0];
        float4 o1 = po4[1];
        float hvv = ws[ob + hvOff];  // psh[lane>>1]
        o0.x *= hvv;  o0.y *= hvv;  o0.z *= hvv;  o0.w *= hvv;
        o1.x *= hvv;  o1.y *= hvv;  o1.z *= hvv;  o1.w *= hvv;
        ((float4*)(orow + i * 256))[0] = o0;
        ((float4*)(orow + i * 256))[1] = o1;
    }
}

extern "C" void kernel_launch(void* const* d_in, const int* in_sizes, int n_in,
                              void* d_out, int out_size) {
    const float* A  = (const float*)d_in[0];
    const float* Bq = (const float*)d_in[1];
    float* O = (float*)d_out;
    int B = in_sizes[0] / 1024;          // [B, 4, 256]
    dim3 grid((B + 7) / 8);
    nalu_kernel<<<grid, 256>>>(A, Bq, O, B);
}